// round 6
// baseline (speedup 1.0000x reference)
#include <cuda_runtime.h>
#include <math.h>
#include <stdint.h>

// Problem shapes (fixed by the dataset)
constexpr int Bb = 16;    // batch
constexpr int Ss = 2048;  // tokens
constexpr int Dd = 512;   // dim
constexpr int Mm = 256;   // memory slots
constexpr int Rr = 64;    // low rank
constexpr float EPS = 1e-5f;
constexpr float STATE_MASS = 4.0f;
constexpr float LRS = 0.1f;

typedef unsigned long long ull;

// ---------------- scratch (static device globals; no allocs) ----------------
__device__ float g_scores[(size_t)Bb * Mm * Ss];   // 33.5 MB (L2-resident) [b][m][s]
__device__ float g_ps[(size_t)Bb * Ss * Rr];       // 8.4 MB   [b*S+s][r]
__device__ float g_mem_val0[(size_t)Mm * Dd];      // LN(init_val), batch-independent
__device__ float g_pt2[(size_t)Mm * Rr];           // (mem_val0@rUt + b) * r_w * 0.1
__device__ float g_mem_state0[Mm];                 // signed-softmax-state(init_state)
__device__ float g_mem_val1[(size_t)Bb * Mm * Dd]; // post-write, post-LN
__device__ float g_state1_raw[(size_t)Bb * Mm];
__device__ float g_state1[(size_t)Bb * Mm];
__device__ float g_qt[(size_t)Bb * Mm * Rr];       // (mem_val1@pUt + b) * p_w * 0.1
__device__ float g_qs2[(size_t)Bb * Mm * Rr];      // (mem_val1@pUs + b) * state1[b,j]

// ---------------- tf32 helpers ----------------
__device__ __forceinline__ uint32_t f2tf32(float x) {
    uint32_t r;
    asm("cvt.rna.tf32.f32 %0, %1;" : "=r"(r) : "f"(x));
    return r;
}

#define MMA_TF32(C, A, B0, B1)                                                  \
    asm volatile(                                                               \
        "mma.sync.aligned.m16n8k8.row.col.f32.tf32.tf32.f32 "                   \
        "{%0,%1,%2,%3}, {%4,%5,%6,%7}, {%8,%9}, {%0,%1,%2,%3};"                 \
        : "+f"((C)[0]), "+f"((C)[1]), "+f"((C)[2]), "+f"((C)[3])                \
        : "r"((A)[0]), "r"((A)[1]), "r"((A)[2]), "r"((A)[3]), "r"(B0), "r"(B1))

// ---------------- shared helpers ----------------
__device__ __forceinline__ void block_ln_512(float a0, float a1, float& mu, float& ri,
                                             float* swr) {
    float ps = a0 + a1;
    float pq = fmaf(a0, a0, a1 * a1);
#pragma unroll
    for (int off = 16; off; off >>= 1) {
        ps += __shfl_down_sync(0xffffffffu, ps, off);
        pq += __shfl_down_sync(0xffffffffu, pq, off);
    }
    int tid = threadIdx.x, wid = tid >> 5, lane = tid & 31;
    if (lane == 0) { swr[wid] = ps; swr[8 + wid] = pq; }
    __syncthreads();
    if (tid == 0) {
        float s = 0.f, q = 0.f;
#pragma unroll
        for (int i = 0; i < 8; i++) { s += swr[i]; q += swr[8 + i]; }
        float m = s * (1.0f / 512.0f);
        float v = q * (1.0f / 512.0f) - m * m;
        swr[16] = m;
        swr[17] = rsqrtf(v + EPS);
    }
    __syncthreads();
    mu = swr[16];
    ri = swr[17];
}

// ---------------- kernel: LayerNorm rows (row length 512) ----------------
__global__ void ln_rows_kernel(const float* __restrict__ in, float* __restrict__ out,
                               const float* __restrict__ g, const float* __restrict__ bta) {
    __shared__ float swr[18];
    int row = blockIdx.x, tid = threadIdx.x;
    const float* x = in + (size_t)row * Dd;
    float a0 = x[tid], a1 = x[tid + 256];
    float mu, ri;
    block_ln_512(a0, a1, mu, ri, swr);
    float* o = out + (size_t)row * Dd;
    o[tid]       = (a0 - mu) * ri * g[tid] + bta[tid];
    o[tid + 256] = (a1 - mu) * ri * g[tid + 256] + bta[tid + 256];
}

// ---------------- kernel: signed softmax state over 256 slots ----------------
__global__ void sss_kernel(const float* __restrict__ in, float* __restrict__ out) {
    int tid = threadIdx.x;
    const float* x = in + (size_t)blockIdx.x * Mm;
    float v = x[tid];
    float a = fabsf(v);
    __shared__ float swr[8];
    __shared__ float s_bc[2];
    int wid = tid >> 5, lane = tid & 31;
    float m = a;
#pragma unroll
    for (int off = 16; off; off >>= 1) m = fmaxf(m, __shfl_down_sync(0xffffffffu, m, off));
    if (lane == 0) swr[wid] = m;
    __syncthreads();
    if (tid == 0) {
        float mm = swr[0];
#pragma unroll
        for (int i = 1; i < 8; i++) mm = fmaxf(mm, swr[i]);
        s_bc[0] = mm;
    }
    __syncthreads();
    float e = expf(a - s_bc[0]);
    float s = e;
#pragma unroll
    for (int off = 16; off; off >>= 1) s += __shfl_down_sync(0xffffffffu, s, off);
    __syncthreads();
    if (lane == 0) swr[wid] = s;
    __syncthreads();
    if (tid == 0) {
        float ss = 0.f;
#pragma unroll
        for (int i = 0; i < 8; i++) ss += swr[i];
        s_bc[1] = ss;
    }
    __syncthreads();
    float sgn = (v > 0.f) ? 1.f : ((v < 0.f) ? -1.f : 0.f);
    out[(size_t)blockIdx.x * Mm + tid] = sgn * e / s_bc[1] * STATE_MASS;
}

// ---------------- scalar tiled projection (small launches: pt2, qt, qs2) ----------------
template <int RT>
__global__ __launch_bounds__(256) void gemm_proj(
    const float* __restrict__ X0,
    float* __restrict__ out0, const float* __restrict__ W0, const float* __restrict__ b0,
    const float* __restrict__ rs0, const float* __restrict__ rowsc0,
    const float* __restrict__ X1,
    float* __restrict__ out1, const float* __restrict__ W1, const float* __restrict__ b1,
    const float* __restrict__ rs1, const float* __restrict__ rowsc1) {
    constexpr int RPT = RT / 16;
    constexpr int XSTR = RT + 4;
    __shared__ float sx[16 * XSTR];
    __shared__ float sw[16 * 68];

    int tid = threadIdx.x;
    int set = blockIdx.y;
    int row0 = blockIdx.x * RT;
    const float* X     = set ? X1 : X0;
    const float* W     = set ? W1 : W0;
    const float* bias  = set ? b1 : b0;
    const float* rs    = set ? rs1 : rs0;
    const float* rowsc = set ? rowsc1 : rowsc0;
    float* out         = set ? out1 : out0;

    int rowg = tid >> 4;
    int colg = tid & 15;

    float acc[RPT][4];
#pragma unroll
    for (int r = 0; r < RPT; r++)
#pragma unroll
        for (int c = 0; c < 4; c++) acc[r][c] = 0.f;

    for (int k0 = 0; k0 < Dd; k0 += 16) {
        constexpr int NV = RT * 16 / 4;
#pragma unroll
        for (int t = 0; t < (NV + 255) / 256; t++) {
            int f = tid + 256 * t;
            if ((NV % 256 == 0) || (f < NV)) {
                int row = f >> 2, q = f & 3;
                float4 v = *(const float4*)&X[(size_t)(row0 + row) * Dd + k0 + 4 * q];
                sx[(4 * q + 0) * XSTR + row] = v.x;
                sx[(4 * q + 1) * XSTR + row] = v.y;
                sx[(4 * q + 2) * XSTR + row] = v.z;
                sx[(4 * q + 3) * XSTR + row] = v.w;
            }
        }
        {
            int k = tid >> 4, c = tid & 15;
            float4 v = *(const float4*)&W[(size_t)(k0 + k) * Rr + 4 * c];
            *(float4*)&sw[k * 68 + 4 * c] = v;
        }
        __syncthreads();
#pragma unroll
        for (int kk = 0; kk < 16; kk++) {
            float4 wv = *(const float4*)&sw[kk * 68 + colg * 4];
            float xr[RPT];
            float2 x0 = *(const float2*)&sx[kk * XSTR + rowg * RPT];
            xr[0] = x0.x; xr[1] = x0.y;
#pragma unroll
            for (int r = 0; r < RPT; r++) {
                acc[r][0] = fmaf(xr[r], wv.x, acc[r][0]);
                acc[r][1] = fmaf(xr[r], wv.y, acc[r][1]);
                acc[r][2] = fmaf(xr[r], wv.z, acc[r][2]);
                acc[r][3] = fmaf(xr[r], wv.w, acc[r][3]);
            }
        }
        __syncthreads();
    }

    float4 bv = *(const float4*)&bias[colg * 4];
    float s0 = 1.f, s1 = 1.f, s2 = 1.f, s3 = 1.f;
    if (rs) {
        float4 rv = *(const float4*)&rs[colg * 4];
        s0 = rv.x * LRS; s1 = rv.y * LRS; s2 = rv.z * LRS; s3 = rv.w * LRS;
    }
#pragma unroll
    for (int r = 0; r < RPT; r++) {
        int row = row0 + rowg * RPT + r;
        float rsc = rowsc ? rowsc[row] : 1.f;
        float4 o;
        o.x = (acc[r][0] + bv.x) * s0 * rsc;
        o.y = (acc[r][1] + bv.y) * s1 * rsc;
        o.z = (acc[r][2] + bv.z) * s2 * rsc;
        o.w = (acc[r][3] + bv.w) * s3 * rsc;
        *(float4*)&out[(size_t)row * Rr + colg * 4] = o;
    }
}

// ---------------- tensor-core ps GEMM: ps[32768,64] = X[32768,512] @ W[512,64] + b ----
// 3xTF32 split. Block 128 rows x 64 cols, 8 warps as 4(m) x 2(n).
// Warp tile 32 rows x 32 cols = 2 m16-tiles x 4 n8-tiles. K chunks of 16 (2 k8 subtiles).
__global__ __launch_bounds__(256) void gemm_ps_tc(
    const float* __restrict__ X, float* __restrict__ out,
    const float* __restrict__ W, const float* __restrict__ bias) {
    __shared__ float sxh[128][20], sxl[128][20];  // X chunk [row][k], pad 20
    __shared__ float swh[16][72], swl[16][72];    // W chunk [k][col], pad 72
    int tid = threadIdx.x, w = tid >> 5, lane = tid & 31;
    int g = lane >> 2, tg = lane & 3;
    int row0 = blockIdx.x * 128;
    int wm = w >> 1, wn = w & 1;

    float acc[2][4][4];
#pragma unroll
    for (int mt = 0; mt < 2; mt++)
#pragma unroll
        for (int nt = 0; nt < 4; nt++)
#pragma unroll
            for (int c = 0; c < 4; c++) acc[mt][nt][c] = 0.f;

    for (int k0 = 0; k0 < Dd; k0 += 16) {
        __syncthreads();
        // stage X chunk: 128 rows x 16 k = 512 float4
#pragma unroll
        for (int t = 0; t < 2; t++) {
            int f = tid + 256 * t;
            int r = f >> 2, q = (f & 3) * 4;
            float4 v = *(const float4*)&X[(size_t)(row0 + r) * Dd + k0 + q];
            float vv[4] = {v.x, v.y, v.z, v.w};
#pragma unroll
            for (int j = 0; j < 4; j++) {
                uint32_t h = f2tf32(vv[j]);
                float hf = __uint_as_float(h);
                sxh[r][q + j] = hf;
                sxl[r][q + j] = __uint_as_float(f2tf32(vv[j] - hf));
            }
        }
        // stage W chunk: 16 k x 64 cols = 256 float4
        {
            int k = tid >> 4, c = (tid & 15) * 4;
            float4 v = *(const float4*)&W[(size_t)(k0 + k) * Rr + c];
            float vv[4] = {v.x, v.y, v.z, v.w};
#pragma unroll
            for (int j = 0; j < 4; j++) {
                uint32_t h = f2tf32(vv[j]);
                float hf = __uint_as_float(h);
                swh[k][c + j] = hf;
                swl[k][c + j] = __uint_as_float(f2tf32(vv[j] - hf));
            }
        }
        __syncthreads();

#pragma unroll
        for (int ks = 0; ks < 2; ks++) {
            int kk = ks * 8;
            uint32_t ah[2][4], al[2][4];
#pragma unroll
            for (int mt = 0; mt < 2; mt++) {
                int r = wm * 32 + mt * 16;
                ah[mt][0] = __float_as_uint(sxh[r + g][kk + tg]);
                ah[mt][1] = __float_as_uint(sxh[r + g + 8][kk + tg]);
                ah[mt][2] = __float_as_uint(sxh[r + g][kk + tg + 4]);
                ah[mt][3] = __float_as_uint(sxh[r + g + 8][kk + tg + 4]);
                al[mt][0] = __float_as_uint(sxl[r + g][kk + tg]);
                al[mt][1] = __float_as_uint(sxl[r + g + 8][kk + tg]);
                al[mt][2] = __float_as_uint(sxl[r + g][kk + tg + 4]);
                al[mt][3] = __float_as_uint(sxl[r + g + 8][kk + tg + 4]);
            }
#pragma unroll
            for (int nt = 0; nt < 4; nt++) {
                int c = wn * 32 + nt * 8 + g;
                uint32_t bh0 = __float_as_uint(swh[kk + tg][c]);
                uint32_t bh1 = __float_as_uint(swh[kk + tg + 4][c]);
                uint32_t bl0 = __float_as_uint(swl[kk + tg][c]);
                uint32_t bl1 = __float_as_uint(swl[kk + tg + 4][c]);
#pragma unroll
                for (int mt = 0; mt < 2; mt++) {
                    MMA_TF32(acc[mt][nt], ah[mt], bh0, bh1);
                    MMA_TF32(acc[mt][nt], ah[mt], bl0, bl1);
                    MMA_TF32(acc[mt][nt], al[mt], bh0, bh1);
                }
            }
        }
    }

    // epilogue: add bias, store (c0,c1) and (c2,c3) as float2
#pragma unroll
    for (int mt = 0; mt < 2; mt++) {
        int r = row0 + wm * 32 + mt * 16 + g;
#pragma unroll
        for (int nt = 0; nt < 4; nt++) {
            int c = wn * 32 + nt * 8 + 2 * tg;
            float b0 = bias[c], b1 = bias[c + 1];
            *(float2*)&out[(size_t)r * Rr + c] =
                make_float2(acc[mt][nt][0] + b0, acc[mt][nt][1] + b1);
            *(float2*)&out[(size_t)(r + 8) * Rr + c] =
                make_float2(acc[mt][nt][2] + b0, acc[mt][nt][3] + b1);
        }
    }
}

// ---------------- tensor-core scores GEMM: scores[b][m][s] = pt2[m] . ps[b][s] ----------
// Block 128 m x 128 s, 8 warps as 4(m) x 2(s): warp tile 32m x 64s = 2 m16 x 8 n8.
// K = 64 in chunks of 16.
__global__ __launch_bounds__(256) void scores_tc_kernel() {
    __shared__ float sah[128][20], sal[128][20];  // pt2 tile [m][k]
    __shared__ float sbh[128][20], sbl[128][20];  // ps tile [s][k]
    int tid = threadIdx.x, w = tid >> 5, lane = tid & 31;
    int g = lane >> 2, tg = lane & 3;
    int b = blockIdx.z;
    int m0 = blockIdx.y * 128;
    int s0 = blockIdx.x * 128;
    int wm = w >> 1, wn = w & 1;

    float acc[2][8][4];
#pragma unroll
    for (int mt = 0; mt < 2; mt++)
#pragma unroll
        for (int nt = 0; nt < 8; nt++)
#pragma unroll
            for (int c = 0; c < 4; c++) acc[mt][nt][c] = 0.f;

    for (int k0 = 0; k0 < Rr; k0 += 16) {
        __syncthreads();
#pragma unroll
        for (int t = 0; t < 2; t++) {
            int f = tid + 256 * t;
            int r = f >> 2, q = (f & 3) * 4;
            float4 va = *(const float4*)&g_pt2[(size_t)(m0 + r) * Rr + k0 + q];
            float av[4] = {va.x, va.y, va.z, va.w};
            float4 vb = *(const float4*)&g_ps[((size_t)b * Ss + s0 + r) * Rr + k0 + q];
            float bv[4] = {vb.x, vb.y, vb.z, vb.w};
#pragma unroll
            for (int j = 0; j < 4; j++) {
                uint32_t h = f2tf32(av[j]);
                float hf = __uint_as_float(h);
                sah[r][q + j] = hf;
                sal[r][q + j] = __uint_as_float(f2tf32(av[j] - hf));
                uint32_t h2 = f2tf32(bv[j]);
                float hf2 = __uint_as_float(h2);
                sbh[r][q + j] = hf2;
                sbl[r][q + j] = __uint_as_float(f2tf32(bv[j] - hf2));
            }
        }
        __syncthreads();

#pragma unroll
        for (int ks = 0; ks < 2; ks++) {
            int kk = ks * 8;
            uint32_t ah[2][4], al[2][4];
#pragma unroll
            for (int mt = 0; mt < 2; mt++) {
                int r = wm * 32 + mt * 16;
                ah[mt][0] = __float_as_uint(sah[r + g][kk + tg]);
                ah[mt][1] = __float_as_uint(sah[r + g + 8][kk + tg]);
                ah[mt][2] = __float_as_uint(sah[r + g][kk + tg + 4]);
                ah[mt][3] = __float_as_uint(sah[r + g + 8][kk + tg + 4]);
                al[mt][0] = __float_as_uint(sal[r + g][kk + tg]);
                al[mt][1] = __float_as_uint(sal[r + g + 8][kk + tg]);
                al[mt][2] = __float_as_uint(sal[r + g][kk + tg + 4]);
                al[mt][3] = __float_as_uint(sal[r + g + 8][kk + tg + 4]);
            }
#pragma unroll
            for (int nt = 0; nt < 8; nt++) {
                int c = wn * 64 + nt * 8 + g;   // s index within tile
                uint32_t bh0 = __float_as_uint(sbh[c][kk + tg]);
                uint32_t bh1 = __float_as_uint(sbh[c][kk + tg + 4]);
                uint32_t bl0 = __float_as_uint(sbl[c][kk + tg]);
                uint32_t bl1 = __float_as_uint(sbl[c][kk + tg + 4]);
#pragma unroll
                for (int mt = 0; mt < 2; mt++) {
                    MMA_TF32(acc[mt][nt], ah[mt], bh0, bh1);
                    MMA_TF32(acc[mt][nt], ah[mt], bl0, bl1);
                    MMA_TF32(acc[mt][nt], al[mt], bh0, bh1);
                }
            }
        }
    }

#pragma unroll
    for (int mt = 0; mt < 2; mt++) {
        int m = m0 + wm * 32 + mt * 16 + g;
#pragma unroll
        for (int nt = 0; nt < 8; nt++) {
            int s = s0 + wn * 64 + nt * 8 + 2 * tg;
            *(float2*)&g_scores[((size_t)(b * Mm + m)) * Ss + s] =
                make_float2(acc[mt][nt][0], acc[mt][nt][1]);
            *(float2*)&g_scores[((size_t)(b * Mm + m + 8)) * Ss + s] =
                make_float2(acc[mt][nt][2], acc[mt][nt][3]);
        }
    }
}

// ---------------- write phase: count-bisection top-16 + edges + gather + LN ----------------
__global__ __launch_bounds__(256) void write_kernel(
    const float* __restrict__ token_val, const float* __restrict__ token_state,
    const float* __restrict__ ln_g, const float* __restrict__ ln_b) {
    int bm = blockIdx.x;
    int b = bm >> 8, m = bm & 255;
    int tid = threadIdx.x, w = tid >> 5, lane = tid & 31;
    __shared__ ull skeys[64];
    __shared__ float swr[18];
    __shared__ int s_ic[8];
    __shared__ int s_tot;
    __shared__ float s_edge[16];
    __shared__ int s_eidx[16];

    const float* row = g_scores + (size_t)bm * Ss;

    float aa[8];
#pragma unroll
    for (int j = 0; j < 8; j++) aa[j] = fabsf(row[tid + 256 * j]);

    {
        unsigned um = 0;
#pragma unroll
        for (int j = 0; j < 8; j++) um = max(um, __float_as_uint(aa[j]));
        um = __reduce_max_sync(0xffffffffu, um);
        if (lane == 0) s_ic[w] = (int)um;
        __syncthreads();
        if (tid == 0) {
            unsigned mm = (unsigned)s_ic[0];
#pragma unroll
            for (int i = 1; i < 8; i++) mm = max(mm, (unsigned)s_ic[i]);
            swr[16] = __uint_as_float(mm);
        }
        __syncthreads();
    }
    float hi = swr[16], lo = 0.f;
    int cl = Ss;

    for (int it = 0; it < 32 && cl > 64; it++) {
        float mid = 0.5f * (lo + hi);
        int c = 0;
#pragma unroll
        for (int j = 0; j < 8; j++) c += (aa[j] > mid);
        c = (int)__reduce_add_sync(0xffffffffu, (unsigned)c);
        if (lane == 0) s_ic[w] = c;
        __syncthreads();
        if (tid == 0) {
            int t = 0;
#pragma unroll
            for (int i = 0; i < 8; i++) t += s_ic[i];
            s_tot = t;
        }
        __syncthreads();
        int tot = s_tot;
        if (tot >= 16) { lo = mid; cl = tot; } else { hi = mid; }
        __syncthreads();
    }

    if (tid == 0) s_tot = 0;
    if (tid < 64) skeys[tid] = 0ull;
    __syncthreads();
#pragma unroll
    for (int j = 0; j < 8; j++) {
        if (aa[j] > lo) {
            int p = atomicAdd(&s_tot, 1);
            if (p < 64)
                skeys[p] = ((ull)__float_as_uint(aa[j]) << 32) | (unsigned)(~(tid + 256 * j));
        }
    }
    __syncthreads();

    for (int k = 2; k <= 64; k <<= 1) {
        for (int j = k >> 1; j; j >>= 1) {
            int i = tid, l = i ^ j;
            if (i < 64 && l > i) {
                ull a = skeys[i], bq = skeys[l];
                bool sw2 = ((i & k) == 0) ? (a < bq) : (a > bq);
                if (sw2) { skeys[i] = bq; skeys[l] = a; }
            }
            __syncthreads();
        }
    }

    if (w == 0) {
        bool valid = lane < 16;
        ull key = skeys[valid ? lane : 0];
        float a = __uint_as_float((unsigned)(key >> 32));
        int idx = (int)(~(unsigned)key);
        float maxa = __shfl_sync(0xffffffffu, a, 0);
        float sel = valid ? row[idx] : 0.f;
        float e = valid ? expf(a - maxa) : 0.f;
        float sum = e;
#pragma unroll
        for (int off = 8; off; off >>= 1) sum += __shfl_xor_sync(0xffffffffu, sum, off, 16);
        float sgn = (sel > 0.f) ? 1.f : ((sel < 0.f) ? -1.f : 0.f);
        float edge = sgn * e / sum;
        if (valid) { s_edge[lane] = edge; s_eidx[lane] = idx; }
        float c = valid ? edge * token_state[(size_t)b * Ss + idx] : 0.f;
#pragma unroll
        for (int off = 8; off; off >>= 1) c += __shfl_xor_sync(0xffffffffu, c, off, 16);
        if (lane == 0) g_state1_raw[bm] = g_mem_state0[m] + c;
    }
    __syncthreads();

    int d = tid;
    float a0 = g_mem_val0[(size_t)m * Dd + d];
    float a1 = g_mem_val0[(size_t)m * Dd + d + 256];
#pragma unroll
    for (int k = 0; k < 16; k++) {
        const float* tv = token_val + ((size_t)b * Ss + s_eidx[k]) * Dd;
        float ek = s_edge[k];
        a0 = fmaf(ek, tv[d], a0);
        a1 = fmaf(ek, tv[d + 256], a1);
    }
    float mu, ri;
    block_ln_512(a0, a1, mu, ri, swr);
    float* o = g_mem_val1 + (size_t)bm * Dd;
    o[d]       = (a0 - mu) * ri * ln_g[d] + ln_b[d];
    o[d + 256] = (a1 - mu) * ri * ln_g[d + 256] + ln_b[d + 256];
}

// ---------------- propagation: 8 rows/block, per-warp bisection top-16 ----------------
__global__ __launch_bounds__(256) void prop8_kernel(
    float* __restrict__ out_final, const float* __restrict__ ln_g,
    const float* __restrict__ ln_b) {
    int b = blockIdx.x >> 5;
    int i0 = (blockIdx.x & 31) * 8;
    int tid = threadIdx.x, w = tid >> 5, lane = tid & 31;
    __shared__ float s_qt[8][68];
    __shared__ float sqs[32][68];
    __shared__ float prow[8][256];
    __shared__ ull wkeys[8][32];
    __shared__ float s_edge[8][16];
    __shared__ int s_eidx[8][16];
    __shared__ float swr[18];

    if (tid < 128) {
        int r = tid >> 4, q = tid & 15;
        *(float4*)&s_qt[r][q * 4] =
            *(const float4*)&g_qt[((size_t)(b * Mm + i0 + r)) * Rr + 4 * q];
    }
    __syncthreads();

    float pv[8];
    for (int j0 = 0; j0 < Mm; j0 += 32) {
#pragma unroll
        for (int t = 0; t < 2; t++) {
            int f = tid + 256 * t;
            int jj = f >> 4, q = f & 15;
            *(float4*)&sqs[jj][q * 4] =
                *(const float4*)&g_qs2[((size_t)(b * Mm + j0 + jj)) * Rr + 4 * q];
        }
        __syncthreads();
        float acc = 0.f;
#pragma unroll
        for (int k4 = 0; k4 < Rr; k4 += 4) {
            float4 qv = *(const float4*)&sqs[lane][k4];
            float4 tv = *(const float4*)&s_qt[w][k4];
            acc = fmaf(qv.x, tv.x, fmaf(qv.y, tv.y, fmaf(qv.z, tv.z, fmaf(qv.w, tv.w, acc))));
        }
        pv[j0 >> 5] = acc;
        prow[w][j0 + lane] = acc;
        __syncthreads();
    }

    float av[8];
#pragma unroll
    for (int r = 0; r < 8; r++) av[r] = fabsf(pv[r]);
    unsigned um = 0;
#pragma unroll
    for (int r = 0; r < 8; r++) um = max(um, __float_as_uint(av[r]));
    um = __reduce_max_sync(0xffffffffu, um);
    float hi = __uint_as_float(um), lo = 0.f;
    int cl = 256;
    for (int it = 0; it < 32 && cl > 32; it++) {
        float mid = 0.5f * (lo + hi);
        int c = 0;
#pragma unroll
        for (int r = 0; r < 8; r++) c += (av[r] > mid);
        c = (int)__reduce_add_sync(0xffffffffu, (unsigned)c);
        if (c >= 16) { lo = mid; cl = c; } else { hi = mid; }
    }

    wkeys[w][lane] = 0ull;
    __syncwarp();
    int base = 0;
#pragma unroll
    for (int r = 0; r < 8; r++) {
        bool p = av[r] > lo;
        unsigned msk = __ballot_sync(0xffffffffu, p);
        if (p) {
            int pos = base + __popc(msk & ((1u << lane) - 1));
            if (pos < 32)
                wkeys[w][pos] =
                    ((ull)__float_as_uint(av[r]) << 32) | (unsigned)(~(r * 32 + lane));
        }
        base += __popc(msk);
    }
    __syncwarp();

    ull key = wkeys[w][lane];
#pragma unroll
    for (int k = 2; k <= 32; k <<= 1) {
#pragma unroll
        for (int j = k >> 1; j; j >>= 1) {
            ull other = __shfl_xor_sync(0xffffffffu, key, j);
            bool dirDesc = ((lane & k) == 0);
            bool upper = (lane & j) != 0;
            bool takeMax = (dirDesc != upper);
            ull mx2 = key > other ? key : other;
            ull mn2 = key > other ? other : key;
            key = takeMax ? mx2 : mn2;
        }
    }

    {
        bool valid = lane < 16;
        float a = __uint_as_float((unsigned)(key >> 32));
        int idx = (int)(~(unsigned)key);
        float maxa = __shfl_sync(0xffffffffu, a, 0);
        float sel = valid ? prow[w][idx] : 0.f;
        float e = valid ? expf(a - maxa) : 0.f;
        float sum = e;
#pragma unroll
        for (int off = 8; off; off >>= 1) sum += __shfl_xor_sync(0xffffffffu, sum, off, 16);
        float sgn = (sel > 0.f) ? 1.f : ((sel < 0.f) ? -1.f : 0.f);
        float edge = sgn * e / sum;
        if (valid) { s_edge[w][lane] = edge; s_eidx[w][lane] = idx; }
    }
    __syncthreads();

    for (int r = 0; r < 8; r++) {
        int bi = b * Mm + i0 + r;
        int d = tid;
        float a0 = g_mem_val1[(size_t)bi * Dd + d];
        float a1 = g_mem_val1[(size_t)bi * Dd + d + 256];
#pragma unroll
        for (int k = 0; k < 16; k++) {
            const float* mv = g_mem_val1 + ((size_t)(b * Mm + s_eidx[r][k])) * Dd;
            float ek = s_edge[r][k];
            a0 = fmaf(ek, mv[d], a0);
            a1 = fmaf(ek, mv[d + 256], a1);
        }
        float mu, ri;
        block_ln_512(a0, a1, mu, ri, swr);
        float* o = out_final + (size_t)bi * Dd;
        o[d]       = (a0 - mu) * ri * ln_g[d] + ln_b[d];
        o[d + 256] = (a1 - mu) * ri * ln_g[d + 256] + ln_b[d + 256];
        __syncthreads();
    }
}

// ---------------- host launch ----------------
extern "C" void kernel_launch(void* const* d_in, const int* in_sizes, int n_in,
                              void* d_out, int out_size) {
    (void)in_sizes; (void)n_in; (void)out_size;
    const float* token_val   = (const float*)d_in[0];
    const float* token_state = (const float*)d_in[1];
    const float* init_state  = (const float*)d_in[2];
    const float* init_val    = (const float*)d_in[3];
    const float* rUs_w = (const float*)d_in[4];
    const float* rUs_b = (const float*)d_in[5];
    const float* rUt_w = (const float*)d_in[6];
    const float* rUt_b = (const float*)d_in[7];
    const float* r_w   = (const float*)d_in[8];
    const float* pUs_w = (const float*)d_in[9];
    const float* pUs_b = (const float*)d_in[10];
    const float* pUt_w = (const float*)d_in[11];
    const float* pUt_b = (const float*)d_in[12];
    const float* p_w   = (const float*)d_in[13];
    const float* ln_g  = (const float*)d_in[14];
    const float* ln_b  = (const float*)d_in[15];
    float* out = (float*)d_out;

    float *p_mv0, *p_pt2, *p_ps, *p_mv1, *p_qt, *p_qs2, *p_st0, *p_st1raw, *p_st1;
    cudaGetSymbolAddress((void**)&p_mv0, g_mem_val0);
    cudaGetSymbolAddress((void**)&p_pt2, g_pt2);
    cudaGetSymbolAddress((void**)&p_ps, g_ps);
    cudaGetSymbolAddress((void**)&p_mv1, g_mem_val1);
    cudaGetSymbolAddress((void**)&p_qt, g_qt);
    cudaGetSymbolAddress((void**)&p_qs2, g_qs2);
    cudaGetSymbolAddress((void**)&p_st0, g_mem_state0);
    cudaGetSymbolAddress((void**)&p_st1raw, g_state1_raw);
    cudaGetSymbolAddress((void**)&p_st1, g_state1);

    // mem_val0 = LN(init_val); mem_state0 = sss(init_state)
    ln_rows_kernel<<<Mm, 256>>>(init_val, p_mv0, ln_g, ln_b);
    sss_kernel<<<1, 256>>>(init_state, p_st0);
    // pt2 = (mem_val0 @ rUt + b) * r_w * 0.1  (scalar, 8 blocks)
    gemm_proj<32><<<dim3(Mm / 32, 1), 256>>>(
        p_mv0, p_pt2, rUt_w, rUt_b, r_w, nullptr,
        nullptr, nullptr, nullptr, nullptr, nullptr, nullptr);
    // ps = token_val @ rUs + b  (tensor cores, 3xTF32)
    gemm_ps_tc<<<(Bb * Ss) / 128, 256>>>(token_val, p_ps, rUs_w, rUs_b);
    // scores = pt2 . ps  (tensor cores, 3xTF32)
    scores_tc_kernel<<<dim3(Ss / 128, Mm / 128, Bb), 256>>>();
    // write phase: bisection topk + edges + gather-add + LN; raw state update
    write_kernel<<<Bb * Mm, 256>>>(token_val, token_state, ln_g, ln_b);
    // state1 = signed_softmax_state(state1_raw)
    sss_kernel<<<Bb, 256>>>(p_st1raw, p_st1);
    // fused: y=0 -> qt ; y=1 -> qs2 (state folded into rows)
    gemm_proj<32><<<dim3((Bb * Mm) / 32, 2), 256>>>(
        p_mv1, p_qt, pUt_w, pUt_b, p_w, nullptr,
        p_mv1, p_qs2, pUs_w, pUs_b, nullptr, p_st1);
    // propagation (8 rows/block, warp bisection) + final LN -> out
    prop8_kernel<<<(Bb * Mm) / 8, 256>>>(out, ln_g, ln_b);
}

// round 8
// speedup vs baseline: 1.0763x; 1.0763x over previous
#include <cuda_runtime.h>
#include <math.h>
#include <stdint.h>

// Problem shapes (fixed by the dataset)
constexpr int Bb = 16;    // batch
constexpr int Ss = 2048;  // tokens
constexpr int Dd = 512;   // dim
constexpr int Mm = 256;   // memory slots
constexpr int Rr = 64;    // low rank
constexpr float EPS = 1e-5f;
constexpr float STATE_MASS = 4.0f;
constexpr float LRS = 0.1f;

typedef unsigned long long ull;

// ---------------- scratch (static device globals; no allocs) ----------------
__device__ float g_scores[(size_t)Bb * Mm * Ss];   // 33.5 MB (L2-resident) [b][m][s]
__device__ float g_ps[(size_t)Bb * Ss * Rr];       // 8.4 MB   [b*S+s][r]
__device__ float g_mem_val0[(size_t)Mm * Dd];      // LN(init_val), batch-independent
__device__ float g_pt2[(size_t)Mm * Rr];           // (mem_val0@rUt + b) * r_w * 0.1
__device__ float g_mem_state0[Mm];                 // signed-softmax-state(init_state)
__device__ float g_mem_val1[(size_t)Bb * Mm * Dd]; // post-write, post-LN
__device__ float g_state1_raw[(size_t)Bb * Mm];
__device__ float g_state1[(size_t)Bb * Mm];
__device__ float g_qt[(size_t)Bb * Mm * Rr];       // (mem_val1@pUt + b) * p_w * 0.1
__device__ float g_qs2[(size_t)Bb * Mm * Rr];      // (mem_val1@pUs + b) * state1[b,j]

// ---------------- tf32 / cp.async helpers ----------------
__device__ __forceinline__ uint32_t f2tf32(float x) {
    uint32_t r;
    asm("cvt.rna.tf32.f32 %0, %1;" : "=r"(r) : "f"(x));
    return r;
}

__device__ __forceinline__ void cpa16(void* dst_smem, const void* src) {
    uint32_t d = (uint32_t)__cvta_generic_to_shared(dst_smem);
    asm volatile("cp.async.ca.shared.global [%0], [%1], 16;" :: "r"(d), "l"(src));
}
#define CP_COMMIT() asm volatile("cp.async.commit_group;")
#define CP_WAIT(n)  asm volatile("cp.async.wait_group %0;" :: "n"(n))

#define MMA_TF32(C, A, B0, B1)                                                  \
    asm volatile(                                                               \
        "mma.sync.aligned.m16n8k8.row.col.f32.tf32.tf32.f32 "                   \
        "{%0,%1,%2,%3}, {%4,%5,%6,%7}, {%8,%9}, {%0,%1,%2,%3};"                 \
        : "+f"((C)[0]), "+f"((C)[1]), "+f"((C)[2]), "+f"((C)[3])                \
        : "r"((A)[0]), "r"((A)[1]), "r"((A)[2]), "r"((A)[3]), "r"(B0), "r"(B1))

// ---------------- shared helpers ----------------
__device__ __forceinline__ void block_ln_512(float a0, float a1, float& mu, float& ri,
                                             float* swr) {
    float ps = a0 + a1;
    float pq = fmaf(a0, a0, a1 * a1);
#pragma unroll
    for (int off = 16; off; off >>= 1) {
        ps += __shfl_down_sync(0xffffffffu, ps, off);
        pq += __shfl_down_sync(0xffffffffu, pq, off);
    }
    int tid = threadIdx.x, wid = tid >> 5, lane = tid & 31;
    if (lane == 0) { swr[wid] = ps; swr[8 + wid] = pq; }
    __syncthreads();
    if (tid == 0) {
        float s = 0.f, q = 0.f;
#pragma unroll
        for (int i = 0; i < 8; i++) { s += swr[i]; q += swr[8 + i]; }
        float m = s * (1.0f / 512.0f);
        float v = q * (1.0f / 512.0f) - m * m;
        swr[16] = m;
        swr[17] = rsqrtf(v + EPS);
    }
    __syncthreads();
    mu = swr[16];
    ri = swr[17];
}

// ---------------- kernel: LayerNorm rows ----------------
__global__ void ln_rows_kernel(const float* __restrict__ in, float* __restrict__ out,
                               const float* __restrict__ g, const float* __restrict__ bta) {
    __shared__ float swr[18];
    int row = blockIdx.x, tid = threadIdx.x;
    const float* x = in + (size_t)row * Dd;
    float a0 = x[tid], a1 = x[tid + 256];
    float mu, ri;
    block_ln_512(a0, a1, mu, ri, swr);
    float* o = out + (size_t)row * Dd;
    o[tid]       = (a0 - mu) * ri * g[tid] + bta[tid];
    o[tid + 256] = (a1 - mu) * ri * g[tid + 256] + bta[tid + 256];
}

// ---------------- kernel: signed softmax state over 256 slots ----------------
__global__ void sss_kernel(const float* __restrict__ in, float* __restrict__ out) {
    int tid = threadIdx.x;
    const float* x = in + (size_t)blockIdx.x * Mm;
    float v = x[tid];
    float a = fabsf(v);
    __shared__ float swr[8];
    __shared__ float s_bc[2];
    int wid = tid >> 5, lane = tid & 31;
    float m = a;
#pragma unroll
    for (int off = 16; off; off >>= 1) m = fmaxf(m, __shfl_down_sync(0xffffffffu, m, off));
    if (lane == 0) swr[wid] = m;
    __syncthreads();
    if (tid == 0) {
        float mm = swr[0];
#pragma unroll
        for (int i = 1; i < 8; i++) mm = fmaxf(mm, swr[i]);
        s_bc[0] = mm;
    }
    __syncthreads();
    float e = expf(a - s_bc[0]);
    float s = e;
#pragma unroll
    for (int off = 16; off; off >>= 1) s += __shfl_down_sync(0xffffffffu, s, off);
    __syncthreads();
    if (lane == 0) swr[wid] = s;
    __syncthreads();
    if (tid == 0) {
        float ss = 0.f;
#pragma unroll
        for (int i = 0; i < 8; i++) ss += swr[i];
        s_bc[1] = ss;
    }
    __syncthreads();
    float sgn = (v > 0.f) ? 1.f : ((v < 0.f) ? -1.f : 0.f);
    out[(size_t)blockIdx.x * Mm + tid] = sgn * e / s_bc[1] * STATE_MASS;
}

// ---------------- scalar tiled projection (small launches: pt2, qt, qs2) ----------------
template <int RT>
__global__ __launch_bounds__(256) void gemm_proj(
    const float* __restrict__ X0,
    float* __restrict__ out0, const float* __restrict__ W0, const float* __restrict__ b0,
    const float* __restrict__ rs0, const float* __restrict__ rowsc0,
    const float* __restrict__ X1,
    float* __restrict__ out1, const float* __restrict__ W1, const float* __restrict__ b1,
    const float* __restrict__ rs1, const float* __restrict__ rowsc1) {
    constexpr int RPT = RT / 16;
    constexpr int XSTR = RT + 4;
    __shared__ float sx[16 * XSTR];
    __shared__ float sw[16 * 68];

    int tid = threadIdx.x;
    int set = blockIdx.y;
    int row0 = blockIdx.x * RT;
    const float* X     = set ? X1 : X0;
    const float* W     = set ? W1 : W0;
    const float* bias  = set ? b1 : b0;
    const float* rs    = set ? rs1 : rs0;
    const float* rowsc = set ? rowsc1 : rowsc0;
    float* out         = set ? out1 : out0;

    int rowg = tid >> 4;
    int colg = tid & 15;

    float acc[RPT][4];
#pragma unroll
    for (int r = 0; r < RPT; r++)
#pragma unroll
        for (int c = 0; c < 4; c++) acc[r][c] = 0.f;

    for (int k0 = 0; k0 < Dd; k0 += 16) {
        constexpr int NV = RT * 16 / 4;
#pragma unroll
        for (int t = 0; t < (NV + 255) / 256; t++) {
            int f = tid + 256 * t;
            if ((NV % 256 == 0) || (f < NV)) {
                int row = f >> 2, q = f & 3;
                float4 v = *(const float4*)&X[(size_t)(row0 + row) * Dd + k0 + 4 * q];
                sx[(4 * q + 0) * XSTR + row] = v.x;
                sx[(4 * q + 1) * XSTR + row] = v.y;
                sx[(4 * q + 2) * XSTR + row] = v.z;
                sx[(4 * q + 3) * XSTR + row] = v.w;
            }
        }
        {
            int k = tid >> 4, c = tid & 15;
            float4 v = *(const float4*)&W[(size_t)(k0 + k) * Rr + 4 * c];
            *(float4*)&sw[k * 68 + 4 * c] = v;
        }
        __syncthreads();
#pragma unroll
        for (int kk = 0; kk < 16; kk++) {
            float4 wv = *(const float4*)&sw[kk * 68 + colg * 4];
            float xr[RPT];
            float2 x0 = *(const float2*)&sx[kk * XSTR + rowg * RPT];
            xr[0] = x0.x; xr[1] = x0.y;
#pragma unroll
            for (int r = 0; r < RPT; r++) {
                acc[r][0] = fmaf(xr[r], wv.x, acc[r][0]);
                acc[r][1] = fmaf(xr[r], wv.y, acc[r][1]);
                acc[r][2] = fmaf(xr[r], wv.z, acc[r][2]);
                acc[r][3] = fmaf(xr[r], wv.w, acc[r][3]);
            }
        }
        __syncthreads();
    }

    float4 bv = *(const float4*)&bias[colg * 4];
    float s0 = 1.f, s1 = 1.f, s2 = 1.f, s3 = 1.f;
    if (rs) {
        float4 rv = *(const float4*)&rs[colg * 4];
        s0 = rv.x * LRS; s1 = rv.y * LRS; s2 = rv.z * LRS; s3 = rv.w * LRS;
    }
#pragma unroll
    for (int r = 0; r < RPT; r++) {
        int row = row0 + rowg * RPT + r;
        float rsc = rowsc ? rowsc[row] : 1.f;
        float4 o;
        o.x = (acc[r][0] + bv.x) * s0 * rsc;
        o.y = (acc[r][1] + bv.y) * s1 * rsc;
        o.z = (acc[r][2] + bv.z) * s2 * rsc;
        o.w = (acc[r][3] + bv.w) * s3 * rsc;
        *(float4*)&out[(size_t)row * Rr + colg * 4] = o;
    }
}

// ---------------- tensor-core ps GEMM, cp.async 3-stage pipeline ----------------
// ps[32768,64] = X[32768,512] @ W[512,64] + b, 3xTF32 split at fragment load.
// Block 128 rows x 64 cols, 8 warps 4(m) x 2(n). K chunks of 16.
__global__ __launch_bounds__(256) void gemm_ps_tc(
    const float* __restrict__ X, float* __restrict__ out,
    const float* __restrict__ W, const float* __restrict__ bias) {
    constexpr int ST = 3;
    __shared__ __align__(16) float sx[ST][128][20];  // raw X chunk [row][k]
    __shared__ __align__(16) float sw[ST][16][72];   // raw W chunk [k][col]
    int tid = threadIdx.x, w = tid >> 5, lane = tid & 31;
    int g = lane >> 2, tg = lane & 3;
    int row0 = blockIdx.x * 128;
    int wm = w >> 1, wn = w & 1;

    int lr = tid >> 2, lq = (tid & 3) * 4;   // X cp.async coords (rows lr, lr+64)
    int wk = tid >> 4, wc = (tid & 15) * 4;  // W cp.async coords

    float acc[2][4][4];
#pragma unroll
    for (int mt = 0; mt < 2; mt++)
#pragma unroll
        for (int nt = 0; nt < 4; nt++)
#pragma unroll
            for (int c = 0; c < 4; c++) acc[mt][nt][c] = 0.f;

    // prologue: chunks 0,1
#pragma unroll
    for (int pc = 0; pc < 2; pc++) {
        int k0 = pc * 16;
        cpa16(&sx[pc][lr][lq],      &X[(size_t)(row0 + lr) * Dd + k0 + lq]);
        cpa16(&sx[pc][lr + 64][lq], &X[(size_t)(row0 + lr + 64) * Dd + k0 + lq]);
        cpa16(&sw[pc][wk][wc],      &W[(size_t)(k0 + wk) * Rr + wc]);
        CP_COMMIT();
    }

    for (int c = 0; c < 32; c++) {
        CP_WAIT(1);
        __syncthreads();
        int stg = c % ST;
#pragma unroll
        for (int ks = 0; ks < 2; ks++) {
            int kk = ks * 8;
            uint32_t ah[2][4], al[2][4];
#pragma unroll
            for (int mt = 0; mt < 2; mt++) {
                int r = wm * 32 + mt * 16;
                float x0 = sx[stg][r + g][kk + tg];
                float x1 = sx[stg][r + g + 8][kk + tg];
                float x2 = sx[stg][r + g][kk + tg + 4];
                float x3 = sx[stg][r + g + 8][kk + tg + 4];
                ah[mt][0] = f2tf32(x0); al[mt][0] = f2tf32(x0 - __uint_as_float(ah[mt][0]));
                ah[mt][1] = f2tf32(x1); al[mt][1] = f2tf32(x1 - __uint_as_float(ah[mt][1]));
                ah[mt][2] = f2tf32(x2); al[mt][2] = f2tf32(x2 - __uint_as_float(ah[mt][2]));
                ah[mt][3] = f2tf32(x3); al[mt][3] = f2tf32(x3 - __uint_as_float(ah[mt][3]));
            }
#pragma unroll
            for (int nt = 0; nt < 4; nt++) {
                int cc = wn * 32 + nt * 8 + g;
                float b0 = sw[stg][kk + tg][cc];
                float b1 = sw[stg][kk + tg + 4][cc];
                uint32_t bh0 = f2tf32(b0), bh1 = f2tf32(b1);
                uint32_t bl0 = f2tf32(b0 - __uint_as_float(bh0));
                uint32_t bl1 = f2tf32(b1 - __uint_as_float(bh1));
#pragma unroll
                for (int mt = 0; mt < 2; mt++) {
                    MMA_TF32(acc[mt][nt], ah[mt], bh0, bh1);
                    MMA_TF32(acc[mt][nt], ah[mt], bl0, bl1);
                    MMA_TF32(acc[mt][nt], al[mt], bh0, bh1);
                }
            }
        }
        __syncthreads();
        int nc = c + 2;
        if (nc < 32) {
            int k0 = nc * 16, s2 = nc % ST;
            cpa16(&sx[s2][lr][lq],      &X[(size_t)(row0 + lr) * Dd + k0 + lq]);
            cpa16(&sx[s2][lr + 64][lq], &X[(size_t)(row0 + lr + 64) * Dd + k0 + lq]);
            cpa16(&sw[s2][wk][wc],      &W[(size_t)(k0 + wk) * Rr + wc]);
        }
        CP_COMMIT();
    }

#pragma unroll
    for (int mt = 0; mt < 2; mt++) {
        int r = row0 + wm * 32 + mt * 16 + g;
#pragma unroll
        for (int nt = 0; nt < 4; nt++) {
            int c = wn * 32 + nt * 8 + 2 * tg;
            float b0 = bias[c], b1 = bias[c + 1];
            *(float2*)&out[(size_t)r * Rr + c] =
                make_float2(acc[mt][nt][0] + b0, acc[mt][nt][1] + b1);
            *(float2*)&out[(size_t)(r + 8) * Rr + c] =
                make_float2(acc[mt][nt][2] + b0, acc[mt][nt][3] + b1);
        }
    }
}

// ---------------- tensor-core scores GEMM, one-shot cp.async staging ----------------
// Block 128 m x 128 s; full K=64 tiles staged once (dynamic smem 69.6 KB).
__global__ __launch_bounds__(256) void scores_tc_kernel() {
    extern __shared__ __align__(16) float smc[];
    float (*sa)[68] = (float(*)[68])smc;               // pt2 tile [m][k]
    float (*sb)[68] = (float(*)[68])(smc + 128 * 68);  // ps  tile [s][k]
    int tid = threadIdx.x, w = tid >> 5, lane = tid & 31;
    int g = lane >> 2, tg = lane & 3;
    int b = blockIdx.z;
    int m0 = blockIdx.y * 128;
    int s0 = blockIdx.x * 128;
    int wm = w >> 1, wn = w & 1;

    // stage both tiles: 2048 float4 each, 8 per thread
#pragma unroll
    for (int t = 0; t < 8; t++) {
        int f = tid + 256 * t;
        int r = f >> 4, q = (f & 15) * 4;
        cpa16(&sa[r][q], &g_pt2[(size_t)(m0 + r) * Rr + q]);
        cpa16(&sb[r][q], &g_ps[((size_t)b * Ss + s0 + r) * Rr + q]);
    }
    CP_COMMIT();

    float acc[2][8][4];
#pragma unroll
    for (int mt = 0; mt < 2; mt++)
#pragma unroll
        for (int nt = 0; nt < 8; nt++)
#pragma unroll
            for (int c = 0; c < 4; c++) acc[mt][nt][c] = 0.f;

    CP_WAIT(0);
    __syncthreads();

#pragma unroll
    for (int ks = 0; ks < 8; ks++) {
        int kk = ks * 8;
        uint32_t ah[2][4], al[2][4];
#pragma unroll
        for (int mt = 0; mt < 2; mt++) {
            int r = wm * 32 + mt * 16;
            float x0 = sa[r + g][kk + tg];
            float x1 = sa[r + g + 8][kk + tg];
            float x2 = sa[r + g][kk + tg + 4];
            float x3 = sa[r + g + 8][kk + tg + 4];
            ah[mt][0] = f2tf32(x0); al[mt][0] = f2tf32(x0 - __uint_as_float(ah[mt][0]));
            ah[mt][1] = f2tf32(x1); al[mt][1] = f2tf32(x1 - __uint_as_float(ah[mt][1]));
            ah[mt][2] = f2tf32(x2); al[mt][2] = f2tf32(x2 - __uint_as_float(ah[mt][2]));
            ah[mt][3] = f2tf32(x3); al[mt][3] = f2tf32(x3 - __uint_as_float(ah[mt][3]));
        }
#pragma unroll
        for (int nt = 0; nt < 8; nt++) {
            int cc = wn * 64 + nt * 8 + g;
            float b0 = sb[cc][kk + tg];
            float b1 = sb[cc][kk + tg + 4];
            uint32_t bh0 = f2tf32(b0), bh1 = f2tf32(b1);
            uint32_t bl0 = f2tf32(b0 - __uint_as_float(bh0));
            uint32_t bl1 = f2tf32(b1 - __uint_as_float(bh1));
#pragma unroll
            for (int mt = 0; mt < 2; mt++) {
                MMA_TF32(acc[mt][nt], ah[mt], bh0, bh1);
                MMA_TF32(acc[mt][nt], ah[mt], bl0, bl1);
                MMA_TF32(acc[mt][nt], al[mt], bh0, bh1);
            }
        }
    }

#pragma unroll
    for (int mt = 0; mt < 2; mt++) {
        int m = m0 + wm * 32 + mt * 16 + g;
#pragma unroll
        for (int nt = 0; nt < 8; nt++) {
            int s = s0 + wn * 64 + nt * 8 + 2 * tg;
            *(float2*)&g_scores[((size_t)(b * Mm + m)) * Ss + s] =
                make_float2(acc[mt][nt][0], acc[mt][nt][1]);
            *(float2*)&g_scores[((size_t)(b * Mm + m + 8)) * Ss + s] =
                make_float2(acc[mt][nt][2], acc[mt][nt][3]);
        }
    }
}

// ---------------- write phase: count-bisection top-16 + edges + gather + LN ----------------
__global__ __launch_bounds__(256) void write_kernel(
    const float* __restrict__ token_val, const float* __restrict__ token_state,
    const float* __restrict__ ln_g, const float* __restrict__ ln_b) {
    int bm = blockIdx.x;
    int b = bm >> 8, m = bm & 255;
    int tid = threadIdx.x, w = tid >> 5, lane = tid & 31;
    __shared__ ull skeys[64];
    __shared__ float swr[18];
    __shared__ int s_ic[8];
    __shared__ int s_tot;
    __shared__ float s_edge[16];
    __shared__ int s_eidx[16];

    const float* row = g_scores + (size_t)bm * Ss;

    float aa[8];
#pragma unroll
    for (int j = 0; j < 8; j++) aa[j] = fabsf(row[tid + 256 * j]);

    {
        unsigned um = 0;
#pragma unroll
        for (int j = 0; j < 8; j++) um = max(um, __float_as_uint(aa[j]));
        um = __reduce_max_sync(0xffffffffu, um);
        if (lane == 0) s_ic[w] = (int)um;
        __syncthreads();
        if (tid == 0) {
            unsigned mm = (unsigned)s_ic[0];
#pragma unroll
            for (int i = 1; i < 8; i++) mm = max(mm, (unsigned)s_ic[i]);
            swr[16] = __uint_as_float(mm);
        }
        __syncthreads();
    }
    float hi = swr[16], lo = 0.f;
    int cl = Ss;

    for (int it = 0; it < 32 && cl > 64; it++) {
        float mid = 0.5f * (lo + hi);
        int c = 0;
#pragma unroll
        for (int j = 0; j < 8; j++) c += (aa[j] > mid);
        c = (int)__reduce_add_sync(0xffffffffu, (unsigned)c);
        if (lane == 0) s_ic[w] = c;
        __syncthreads();
        if (tid == 0) {
            int t = 0;
#pragma unroll
            for (int i = 0; i < 8; i++) t += s_ic[i];
            s_tot = t;
        }
        __syncthreads();
        int tot = s_tot;
        if (tot >= 16) { lo = mid; cl = tot; } else { hi = mid; }
        __syncthreads();
    }

    if (tid == 0) s_tot = 0;
    if (tid < 64) skeys[tid] = 0ull;
    __syncthreads();
#pragma unroll
    for (int j = 0; j < 8; j++) {
        if (aa[j] > lo) {
            int p = atomicAdd(&s_tot, 1);
            if (p < 64)
                skeys[p] = ((ull)__float_as_uint(aa[j]) << 32) | (unsigned)(~(tid + 256 * j));
        }
    }
    __syncthreads();

    for (int k = 2; k <= 64; k <<= 1) {
        for (int j = k >> 1; j; j >>= 1) {
            int i = tid, l = i ^ j;
            if (i < 64 && l > i) {
                ull a = skeys[i], bq = skeys[l];
                bool sw2 = ((i & k) == 0) ? (a < bq) : (a > bq);
                if (sw2) { skeys[i] = bq; skeys[l] = a; }
            }
            __syncthreads();
        }
    }

    if (w == 0) {
        bool valid = lane < 16;
        ull key = skeys[valid ? lane : 0];
        float a = __uint_as_float((unsigned)(key >> 32));
        int idx = (int)(~(unsigned)key);
        float maxa = __shfl_sync(0xffffffffu, a, 0);
        float sel = valid ? row[idx] : 0.f;
        float e = valid ? expf(a - maxa) : 0.f;
        float sum = e;
#pragma unroll
        for (int off = 8; off; off >>= 1) sum += __shfl_xor_sync(0xffffffffu, sum, off, 16);
        float sgn = (sel > 0.f) ? 1.f : ((sel < 0.f) ? -1.f : 0.f);
        float edge = sgn * e / sum;
        if (valid) { s_edge[lane] = edge; s_eidx[lane] = idx; }
        float c = valid ? edge * token_state[(size_t)b * Ss + idx] : 0.f;
#pragma unroll
        for (int off = 8; off; off >>= 1) c += __shfl_xor_sync(0xffffffffu, c, off, 16);
        if (lane == 0) g_state1_raw[bm] = g_mem_state0[m] + c;
    }
    __syncthreads();

    int d = tid;
    float a0 = g_mem_val0[(size_t)m * Dd + d];
    float a1 = g_mem_val0[(size_t)m * Dd + d + 256];
#pragma unroll
    for (int k = 0; k < 16; k++) {
        const float* tv = token_val + ((size_t)b * Ss + s_eidx[k]) * Dd;
        float ek = s_edge[k];
        a0 = fmaf(ek, tv[d], a0);
        a1 = fmaf(ek, tv[d + 256], a1);
    }
    float mu, ri;
    block_ln_512(a0, a1, mu, ri, swr);
    float* o = g_mem_val1 + (size_t)bm * Dd;
    o[d]       = (a0 - mu) * ri * ln_g[d] + ln_b[d];
    o[d + 256] = (a1 - mu) * ri * ln_g[d + 256] + ln_b[d + 256];
}

// ---------------- propagation: 8 rows/block, per-warp bisection top-16 ----------------
__global__ __launch_bounds__(256) void prop8_kernel(
    float* __restrict__ out_final, const float* __restrict__ ln_g,
    const float* __restrict__ ln_b) {
    int b = blockIdx.x >> 5;
    int i0 = (blockIdx.x & 31) * 8;
    int tid = threadIdx.x, w = tid >> 5, lane = tid & 31;
    __shared__ float s_qt[8][68];
    __shared__ float sqs[32][68];
    __shared__ float prow[8][256];
    __shared__ ull wkeys[8][32];
    __shared__ float s_edge[8][16];
    __shared__ int s_eidx[8][16];
    __shared__ float swr[18];

    if (tid < 128) {
        int r = tid >> 4, q = tid & 15;
        *(float4*)&s_qt[r][q * 4] =
            *(const float4*)&g_qt[((size_t)(b * Mm + i0 + r)) * Rr + 4 * q];
    }
    __syncthreads();

    float pv[8];
    for (int j0 = 0; j0 < Mm; j0 += 32) {
#pragma unroll
        for (int t = 0; t < 2; t++) {
            int f = tid + 256 * t;
            int jj = f >> 4, q = f & 15;
            *(float4*)&sqs[jj][q * 4] =
                *(const float4*)&g_qs2[((size_t)(b * Mm + j0 + jj)) * Rr + 4 * q];
        }
        __syncthreads();
        float acc = 0.f;
#pragma unroll
        for (int k4 = 0; k4 < Rr; k4 += 4) {
            float4 qv = *(const float4*)&sqs[lane][k4];
            float4 tv = *(const float4*)&s_qt[w][k4];
            acc = fmaf(qv.x, tv.x, fmaf(qv.y, tv.y, fmaf(qv.z, tv.z, fmaf(qv.w, tv.w, acc))));
        }
        pv[j0 >> 5] = acc;
        prow[w][j0 + lane] = acc;
        __syncthreads();
    }

    float av[8];
#pragma unroll
    for (int r = 0; r < 8; r++) av[r] = fabsf(pv[r]);
    unsigned um = 0;
#pragma unroll
    for (int r = 0; r < 8; r++) um = max(um, __float_as_uint(av[r]));
    um = __reduce_max_sync(0xffffffffu, um);
    float hi = __uint_as_float(um), lo = 0.f;
    int cl = 256;
    for (int it = 0; it < 32 && cl > 32; it++) {
        float mid = 0.5f * (lo + hi);
        int c = 0;
#pragma unroll
        for (int r = 0; r < 8; r++) c += (av[r] > mid);
        c = (int)__reduce_add_sync(0xffffffffu, (unsigned)c);
        if (c >= 16) { lo = mid; cl = c; } else { hi = mid; }
    }

    wkeys[w][lane] = 0ull;
    __syncwarp();
    int base = 0;
#pragma unroll
    for (int r = 0; r < 8; r++) {
        bool p = av[r] > lo;
        unsigned msk = __ballot_sync(0xffffffffu, p);
        if (p) {
            int pos = base + __popc(msk & ((1u << lane) - 1));
            if (pos < 32)
                wkeys[w][pos] =
                    ((ull)__float_as_uint(av[r]) << 32) | (unsigned)(~(r * 32 + lane));
        }
        base += __popc(msk);
    }
    __syncwarp();

    ull key = wkeys[w][lane];
#pragma unroll
    for (int k = 2; k <= 32; k <<= 1) {
#pragma unroll
        for (int j = k >> 1; j; j >>= 1) {
            ull other = __shfl_xor_sync(0xffffffffu, key, j);
            bool dirDesc = ((lane & k) == 0);
            bool upper = (lane & j) != 0;
            bool takeMax = (dirDesc != upper);
            ull mx2 = key > other ? key : other;
            ull mn2 = key > other ? other : key;
            key = takeMax ? mx2 : mn2;
        }
    }

    {
        bool valid = lane < 16;
        float a = __uint_as_float((unsigned)(key >> 32));
        int idx = (int)(~(unsigned)key);
        float maxa = __shfl_sync(0xffffffffu, a, 0);
        float sel = valid ? prow[w][idx] : 0.f;
        float e = valid ? expf(a - maxa) : 0.f;
        float sum = e;
#pragma unroll
        for (int off = 8; off; off >>= 1) sum += __shfl_xor_sync(0xffffffffu, sum, off, 16);
        float sgn = (sel > 0.f) ? 1.f : ((sel < 0.f) ? -1.f : 0.f);
        float edge = sgn * e / sum;
        if (valid) { s_edge[w][lane] = edge; s_eidx[w][lane] = idx; }
    }
    __syncthreads();

    for (int r = 0; r < 8; r++) {
        int bi = b * Mm + i0 + r;
        int d = tid;
        float a0 = g_mem_val1[(size_t)bi * Dd + d];
        float a1 = g_mem_val1[(size_t)bi * Dd + d + 256];
#pragma unroll
        for (int k = 0; k < 16; k++) {
            const float* mv = g_mem_val1 + ((size_t)(b * Mm + s_eidx[r][k])) * Dd;
            float ek = s_edge[r][k];
            a0 = fmaf(ek, mv[d], a0);
            a1 = fmaf(ek, mv[d + 256], a1);
        }
        float mu, ri;
        block_ln_512(a0, a1, mu, ri, swr);
        float* o = out_final + (size_t)bi * Dd;
        o[d]       = (a0 - mu) * ri * ln_g[d] + ln_b[d];
        o[d + 256] = (a1 - mu) * ri * ln_g[d + 256] + ln_b[d + 256];
        __syncthreads();
    }
}

// ---------------- host launch ----------------
extern "C" void kernel_launch(void* const* d_in, const int* in_sizes, int n_in,
                              void* d_out, int out_size) {
    (void)in_sizes; (void)n_in; (void)out_size;
    const float* token_val   = (const float*)d_in[0];
    const float* token_state = (const float*)d_in[1];
    const float* init_state  = (const float*)d_in[2];
    const float* init_val    = (const float*)d_in[3];
    const float* rUs_w = (const float*)d_in[4];
    const float* rUs_b = (const float*)d_in[5];
    const float* rUt_w = (const float*)d_in[6];
    const float* rUt_b = (const float*)d_in[7];
    const float* r_w   = (const float*)d_in[8];
    const float* pUs_w = (const float*)d_in[9];
    const float* pUs_b = (const float*)d_in[10];
    const float* pUt_w = (const float*)d_in[11];
    const float* pUt_b = (const float*)d_in[12];
    const float* p_w   = (const float*)d_in[13];
    const float* ln_g  = (const float*)d_in[14];
    const float* ln_b  = (const float*)d_in[15];
    float* out = (float*)d_out;

    float *p_mv0, *p_pt2, *p_ps, *p_mv1, *p_qt, *p_qs2, *p_st0, *p_st1raw, *p_st1;
    cudaGetSymbolAddress((void**)&p_mv0, g_mem_val0);
    cudaGetSymbolAddress((void**)&p_pt2, g_pt2);
    cudaGetSymbolAddress((void**)&p_ps, g_ps);
    cudaGetSymbolAddress((void**)&p_mv1, g_mem_val1);
    cudaGetSymbolAddress((void**)&p_qt, g_qt);
    cudaGetSymbolAddress((void**)&p_qs2, g_qs2);
    cudaGetSymbolAddress((void**)&p_st0, g_mem_state0);
    cudaGetSymbolAddress((void**)&p_st1raw, g_state1_raw);
    cudaGetSymbolAddress((void**)&p_st1, g_state1);

    const int SC_SMEM = 2 * 128 * 68 * 4;  // 69632 bytes
    cudaFuncSetAttribute(scores_tc_kernel,
                         cudaFuncAttributeMaxDynamicSharedMemorySize, SC_SMEM);

    // mem_val0 = LN(init_val); mem_state0 = sss(init_state)
    ln_rows_kernel<<<Mm, 256>>>(init_val, p_mv0, ln_g, ln_b);
    sss_kernel<<<1, 256>>>(init_state, p_st0);
    // pt2 = (mem_val0 @ rUt + b) * r_w * 0.1  (scalar, 8 blocks)
    gemm_proj<32><<<dim3(Mm / 32, 1), 256>>>(
        p_mv0, p_pt2, rUt_w, rUt_b, r_w, nullptr,
        nullptr, nullptr, nullptr, nullptr, nullptr, nullptr);
    // ps = token_val @ rUs + b  (tensor cores, cp.async pipelined)
    gemm_ps_tc<<<(Bb * Ss) / 128, 256>>>(token_val, p_ps, rUs_w, rUs_b);
    // scores = pt2 . ps  (tensor cores, one-shot staged)
    scores_tc_kernel<<<dim3(Ss / 128, Mm / 128, Bb), 256, SC_SMEM>>>();
    // write phase: bisection topk + edges + gather-add + LN; raw state update
    write_kernel<<<Bb * Mm, 256>>>(token_val, token_state, ln_g, ln_b);
    // state1 = signed_softmax_state(state1_raw)
    sss_kernel<<<Bb, 256>>>(p_st1raw, p_st1);
    // fused: y=0 -> qt ; y=1 -> qs2 (state folded into rows)
    gemm_proj<32><<<dim3((Bb * Mm) / 32, 2), 256>>>(
        p_mv1, p_qt, pUt_w, pUt_b, p_w, nullptr,
        p_mv1, p_qs2, pUs_w, pUs_b, nullptr, p_st1);
    // propagation (8 rows/block, warp bisection) + final LN -> out
    prop8_kernel<<<(Bb * Mm) / 8, 256>>>(out, ln_g, ln_b);
}